// round 2
// baseline (speedup 1.0000x reference)
#include <cuda_runtime.h>
#include <cuda_bf16.h>
#include <cstdint>
#include <math.h>

// Problem: LSTM  B=128, S=256, I=1024, H=1024
// out[b,s,h] fp32
//
// Phase 1: Xp[s][b][4H] = x[b,s,:] @ Wx^T + bias   (parallel GEMM, tf32 mma)
// Phase 2: persistent 128-CTA kernel scans 256 steps:
//          gates = Xp[t] + h_t @ Wh^T ; LSTM cell update; grid barrier per step.

#define NBLK2 128            // persistent blocks (1 per SM guaranteed by smem)
#define WS_STRIDE 1028       // 1024 + 4 pad (u32)
#define AS_STRIDE 68         // 64 + 4 pad (u32)
#define SMEM2_BYTES (32*WS_STRIDE*4 + 128*AS_STRIDE*4 + 128*8*4)

__device__ __align__(16) float g_Xp[(size_t)256 * 128 * 4096];   // 512 MB scratch
__device__ __align__(16) float g_h[2 * 128 * 1024];              // double-buffered h
__device__ unsigned g_arrive = 0;                                // monotone barrier ctr

__device__ __forceinline__ uint32_t f2tf32(float f) {
    uint32_t u;
    asm volatile("cvt.rna.tf32.f32 %0, %1;" : "=r"(u) : "f"(f));
    return u;
}

__device__ __forceinline__ void mma_tf32(float d[4], const uint32_t a[4], const uint32_t b[2]) {
    asm volatile(
        "mma.sync.aligned.m16n8k8.row.col.f32.tf32.tf32.f32 "
        "{%0,%1,%2,%3},{%4,%5,%6,%7},{%8,%9},{%0,%1,%2,%3};"
        : "+f"(d[0]), "+f"(d[1]), "+f"(d[2]), "+f"(d[3])
        : "r"(a[0]), "r"(a[1]), "r"(a[2]), "r"(a[3]), "r"(b[0]), "r"(b[1]));
}

__device__ __forceinline__ float sigm(float x) { return 1.0f / (1.0f + expf(-x)); }

// ---------------------------------------------------------------------------
// Phase 1: Xp = x @ Wx^T + bias.  M=32768 (b*256+s), N=4096 (gate*1024+r), K=1024
// Block tile 128x64, BK=32, 8 warps (4m x 2n), warp tile 32x32.
// ---------------------------------------------------------------------------
__global__ __launch_bounds__(256) void xproj_kernel(
    const float* __restrict__ x,
    const float* __restrict__ Wf, const float* __restrict__ bf,
    const float* __restrict__ Wi, const float* __restrict__ bi,
    const float* __restrict__ Wc, const float* __restrict__ bc,
    const float* __restrict__ Wo, const float* __restrict__ bo)
{
    __shared__ uint32_t As[128][36];
    __shared__ uint32_t Bs[64][36];

    const float* Wsel[4] = {Wf, Wi, Wc, Wo};
    const float* bsel[4] = {bf, bi, bc, bo};

    const int tid  = threadIdx.x;
    const int warp = tid >> 5;
    const int lane = tid & 31;
    const int q = lane >> 2, p = lane & 3;
    const int wm = warp & 3;       // 0..3
    const int wn = warp >> 2;      // 0..1
    const int m0 = blockIdx.x * 128;
    const int gate = blockIdx.y >> 4;
    const int r0 = (blockIdx.y & 15) * 64;
    const float* __restrict__ Wg = Wsel[gate];
    const float* __restrict__ bg = bsel[gate];

    float acc[2][4][4];
    #pragma unroll
    for (int mt = 0; mt < 2; ++mt)
        #pragma unroll
        for (int nt = 0; nt < 4; ++nt)
            #pragma unroll
            for (int r = 0; r < 4; ++r) acc[mt][nt][r] = 0.0f;

    for (int k0 = 0; k0 < 1024; k0 += 32) {
        // load A tile 128x32 (x rows are m = b*256+s, contiguous K)
        #pragma unroll
        for (int it = 0; it < 4; ++it) {
            int f = tid + 256 * it;
            int row = f >> 3;
            int c4 = (f & 7) * 4;
            float4 v = *reinterpret_cast<const float4*>(
                &x[(size_t)(m0 + row) * 1024 + k0 + c4]);
            As[row][c4 + 0] = f2tf32(v.x);
            As[row][c4 + 1] = f2tf32(v.y);
            As[row][c4 + 2] = f2tf32(v.z);
            As[row][c4 + 3] = f2tf32(v.w);
        }
        // load B tile 64x32 from Wx part (cols 1024..2047 of W[n,:])
        #pragma unroll
        for (int it = 0; it < 2; ++it) {
            int f = tid + 256 * it;
            int row = f >> 3;
            int c4 = (f & 7) * 4;
            float4 v = *reinterpret_cast<const float4*>(
                &Wg[(size_t)(r0 + row) * 2048 + 1024 + k0 + c4]);
            Bs[row][c4 + 0] = f2tf32(v.x);
            Bs[row][c4 + 1] = f2tf32(v.y);
            Bs[row][c4 + 2] = f2tf32(v.z);
            Bs[row][c4 + 3] = f2tf32(v.w);
        }
        __syncthreads();

        #pragma unroll
        for (int ks = 0; ks < 4; ++ks) {
            const int kk = ks * 8;
            uint32_t a[2][4];
            #pragma unroll
            for (int mt = 0; mt < 2; ++mt) {
                int rb = wm * 32 + mt * 16 + q;
                a[mt][0] = As[rb][kk + p];
                a[mt][1] = As[rb + 8][kk + p];
                a[mt][2] = As[rb][kk + p + 4];
                a[mt][3] = As[rb + 8][kk + p + 4];
            }
            #pragma unroll
            for (int nt = 0; nt < 4; ++nt) {
                uint32_t bb[2];
                int nr = wn * 32 + nt * 8 + q;
                bb[0] = Bs[nr][kk + p];
                bb[1] = Bs[nr][kk + p + 4];
                mma_tf32(acc[0][nt], a[0], bb);
                mma_tf32(acc[1][nt], a[1], bb);
            }
        }
        __syncthreads();
    }

    // epilogue: add bias, store to Xp[s][b][gate*1024 + n]
    #pragma unroll
    for (int mt = 0; mt < 2; ++mt)
        #pragma unroll
        for (int nt = 0; nt < 4; ++nt)
            #pragma unroll
            for (int r = 0; r < 4; ++r) {
                int row = wm * 32 + mt * 16 + q + ((r >> 1) << 3);
                int col = wn * 32 + nt * 8 + 2 * p + (r & 1);
                int m = m0 + row;
                int b = m >> 8;        // m / 256
                int s = m & 255;       // m % 256
                float v = acc[mt][nt][r] + bg[r0 + col];
                g_Xp[((size_t)(s * 128 + b) * 4096) + gate * 1024 + r0 + col] = v;
            }
}

// ---------------------------------------------------------------------------
// Phase 2: persistent scan. 128 blocks x 256 threads. Block bx owns
// h-columns j0..j0+7 and the 4 gate columns for each (32 output cols total).
// Wh slice (32 x 1024, tf32) persistent in smem. c state in smem.
// ---------------------------------------------------------------------------
__device__ __forceinline__ void grid_barrier() {
    __threadfence();
    if (threadIdx.x == 0) {
        unsigned old = atomicAdd(&g_arrive, 1u);
        unsigned target = (old / gridDim.x + 1u) * gridDim.x;
        while (*(volatile unsigned*)&g_arrive < target) {
            __nanosleep(64);
        }
        __threadfence();
    }
    __syncthreads();
}

__global__ void __launch_bounds__(256, 1) lstm_scan_kernel(
    const float* __restrict__ Wf, const float* __restrict__ Wi,
    const float* __restrict__ Wc, const float* __restrict__ Wo,
    float* __restrict__ out)
{
    extern __shared__ uint8_t smem[];
    uint32_t* Ws = reinterpret_cast<uint32_t*>(smem);                       // [32][WS_STRIDE]
    uint32_t* As = reinterpret_cast<uint32_t*>(smem + 32 * WS_STRIDE * 4);  // [128][AS_STRIDE]
    float*    cs = reinterpret_cast<float*>(smem + 32 * WS_STRIDE * 4 + 128 * AS_STRIDE * 4); // [128][8]

    const float* Wsel[4] = {Wf, Wi, Wc, Wo};
    const int tid  = threadIdx.x;
    const int warp = tid >> 5;
    const int lane = tid & 31;
    const int q = lane >> 2, p = lane & 3;
    const int j0 = blockIdx.x * 8;

    // Load Wh slice (cols 0..1023 of W rows j0..j0+7 per gate) as tf32.
    for (int idx = tid; idx < 32 * 256; idx += 256) {
        int cc = idx >> 8;          // 0..31 : gate*8 + jj
        int k4 = (idx & 255) * 4;
        int g = cc >> 3, jj = cc & 7;
        const float* Wg = Wsel[g];
        float4 v = *reinterpret_cast<const float4*>(&Wg[(size_t)(j0 + jj) * 2048 + k4]);
        uint32_t* wr = &Ws[cc * WS_STRIDE + k4];
        wr[0] = f2tf32(v.x); wr[1] = f2tf32(v.y); wr[2] = f2tf32(v.z); wr[3] = f2tf32(v.w);
    }
    // zero c state and h buffer 0 (our columns)
    for (int idx = tid; idx < 1024; idx += 256) {
        cs[idx] = 0.0f;
        int b = idx >> 3, jj = idx & 7;
        g_h[b * 1024 + j0 + jj] = 0.0f;
    }
    grid_barrier();

    for (int t = 0; t < 256; ++t) {
        const float* __restrict__ hin = &g_h[(t & 1) * (128 * 1024)];
        float* __restrict__ hout = &g_h[((t + 1) & 1) * (128 * 1024)];

        float acc[4][4];
        #pragma unroll
        for (int nt = 0; nt < 4; ++nt)
            #pragma unroll
            for (int r = 0; r < 4; ++r) acc[nt][r] = 0.0f;

        for (int chunk = 0; chunk < 16; ++chunk) {
            __syncthreads();
            // stage h[:, chunk*64 .. +64] as tf32 (bypass L1 with ldcg)
            #pragma unroll
            for (int it = 0; it < 8; ++it) {
                int f = tid + 256 * it;
                int row = f >> 4;
                int c4 = (f & 15) * 4;
                float4 v = __ldcg(reinterpret_cast<const float4*>(
                    &hin[row * 1024 + chunk * 64 + c4]));
                uint32_t* wr = &As[row * AS_STRIDE + c4];
                wr[0] = f2tf32(v.x); wr[1] = f2tf32(v.y);
                wr[2] = f2tf32(v.z); wr[3] = f2tf32(v.w);
            }
            __syncthreads();

            #pragma unroll
            for (int ks = 0; ks < 8; ++ks) {
                const int kk = ks * 8;
                const int kg = chunk * 64 + kk;
                uint32_t a[4];
                int rb = warp * 16 + q;
                a[0] = As[rb * AS_STRIDE + kk + p];
                a[1] = As[(rb + 8) * AS_STRIDE + kk + p];
                a[2] = As[rb * AS_STRIDE + kk + p + 4];
                a[3] = As[(rb + 8) * AS_STRIDE + kk + p + 4];
                #pragma unroll
                for (int nt = 0; nt < 4; ++nt) {
                    uint32_t bb[2];
                    int nr = nt * 8 + q;
                    bb[0] = Ws[nr * WS_STRIDE + kg + p];
                    bb[1] = Ws[nr * WS_STRIDE + kg + p + 4];
                    mma_tf32(acc[nt], a, bb);
                }
            }
        }

        // epilogue: gates -> cell update -> h
        #pragma unroll
        for (int r = 0; r < 4; ++r) {
            int row = warp * 16 + q + ((r >> 1) << 3);   // batch index 0..127
            int jj = 2 * p + (r & 1);                    // 0..7
            size_t xb = ((size_t)(t * 128 + row)) * 4096 + j0 + jj;
            float fp = acc[0][r] + __ldg(&g_Xp[xb]);
            float ip = acc[1][r] + __ldg(&g_Xp[xb + 1024]);
            float gp = acc[2][r] + __ldg(&g_Xp[xb + 2048]);
            float op = acc[3][r] + __ldg(&g_Xp[xb + 3072]);
            float fg = sigm(fp);
            float ig = sigm(ip);
            float gg = tanhf(gp);
            float og = sigm(op);
            float cnew = cs[row * 8 + jj] * fg + ig * gg;
            cs[row * 8 + jj] = cnew;
            float hnew = tanhf(cnew) * og;
            hout[row * 1024 + j0 + jj] = hnew;
            out[(size_t)row * (256 * 1024) + t * 1024 + j0 + jj] = hnew;
        }
        grid_barrier();
    }
}

// ---------------------------------------------------------------------------
extern "C" void kernel_launch(void* const* d_in, const int* in_sizes, int n_in,
                              void* d_out, int out_size) {
    const float* x  = (const float*)d_in[0];
    const float* Wf = (const float*)d_in[1];
    const float* bf = (const float*)d_in[2];
    const float* Wi = (const float*)d_in[3];
    const float* bi = (const float*)d_in[4];
    const float* Wc = (const float*)d_in[5];
    const float* bc = (const float*)d_in[6];
    const float* Wo = (const float*)d_in[7];
    const float* bo = (const float*)d_in[8];
    float* out = (float*)d_out;

    cudaFuncSetAttribute(lstm_scan_kernel,
                         cudaFuncAttributeMaxDynamicSharedMemorySize, SMEM2_BYTES);

    dim3 g1(32768 / 128, 4096 / 64);
    xproj_kernel<<<g1, 256>>>(x, Wf, bf, Wi, bi, Wc, bc, Wo, bo);
    lstm_scan_kernel<<<NBLK2, 256, SMEM2_BYTES>>>(Wf, Wi, Wc, Wo, out);
}

// round 3
// speedup vs baseline: 1.3187x; 1.3187x over previous
#include <cuda_runtime.h>
#include <cuda_bf16.h>
#include <cstdint>
#include <math.h>

// LSTM B=128, S=256, I=1024, H=1024. out[b,s,h] fp32.
// Phase 1: Xp[s][b][4H] = x @ Wx^T + bias (tf32 mma, pipelined)
// Phase 2: persistent 128-CTA scan, cp.async-pipelined h broadcast,
//          4(m)x2(k) warp split, smem reduction, grid barrier per step.

#define NBLK2 128
#define WS_STRIDE 1028               // 1024 + 4 pad (u32)
#define AS_STRIDE 68                 // 64 + 4 pad (u32), row = 272B (16B-aligned)
#define SMEM2_BYTES (32*WS_STRIDE*4 + 2*128*AS_STRIDE*4)   // 201,216 B

__device__ __align__(16) float    g_Xp[(size_t)256 * 128 * 4096];  // 512 MB
__device__ __align__(16) uint32_t g_h[2 * 128 * 1024];             // h as tf32 bits, dbl buf
__device__ unsigned g_arrive = 0;

__device__ __forceinline__ uint32_t f2tf32(float f) {
    uint32_t u;
    asm volatile("cvt.rna.tf32.f32 %0, %1;" : "=r"(u) : "f"(f));
    return u;
}

__device__ __forceinline__ void mma_tf32(float d[4], const uint32_t a[4], const uint32_t b[2]) {
    asm volatile(
        "mma.sync.aligned.m16n8k8.row.col.f32.tf32.tf32.f32 "
        "{%0,%1,%2,%3},{%4,%5,%6,%7},{%8,%9},{%0,%1,%2,%3};"
        : "+f"(d[0]), "+f"(d[1]), "+f"(d[2]), "+f"(d[3])
        : "r"(a[0]), "r"(a[1]), "r"(a[2]), "r"(a[3]), "r"(b[0]), "r"(b[1]));
}

__device__ __forceinline__ float sigm(float x) { return 1.0f / (1.0f + expf(-x)); }

// ---------------------------------------------------------------------------
// Phase 1: block tile 128x64, BK=32, 8 warps (4m x 2n). Register-staged pipeline.
// grid: x = n-blocks (64) [inner, for x-row L2 reuse], y = m-blocks (256)
// ---------------------------------------------------------------------------
__global__ __launch_bounds__(256) void xproj_kernel(
    const float* __restrict__ x,
    const float* __restrict__ Wf, const float* __restrict__ bf,
    const float* __restrict__ Wi, const float* __restrict__ bi,
    const float* __restrict__ Wc, const float* __restrict__ bc,
    const float* __restrict__ Wo, const float* __restrict__ bo)
{
    __shared__ uint32_t As[128][36];
    __shared__ uint32_t Bs[64][36];

    const float* Wsel[4] = {Wf, Wi, Wc, Wo};
    const float* bsel[4] = {bf, bi, bc, bo};

    const int tid  = threadIdx.x;
    const int warp = tid >> 5;
    const int lane = tid & 31;
    const int q = lane >> 2, p = lane & 3;
    const int wm = warp & 3;
    const int wn = warp >> 2;
    const int gate = blockIdx.x >> 4;
    const int r0 = (blockIdx.x & 15) * 64;
    const int m0 = blockIdx.y * 128;
    const float* __restrict__ Wg = Wsel[gate];
    const float* __restrict__ bg = bsel[gate];

    // per-thread load indices
    const int arow[4] = { (tid) >> 3, (tid+256) >> 3, (tid+512) >> 3, (tid+768) >> 3 };
    const int ac4 = (tid & 7) * 4;

    float acc[2][4][4];
    #pragma unroll
    for (int mt = 0; mt < 2; ++mt)
        #pragma unroll
        for (int nt = 0; nt < 4; ++nt)
            #pragma unroll
            for (int r = 0; r < 4; ++r) acc[mt][nt][r] = 0.0f;

    float4 ar[4], br[2];

    // prologue: load k-tile 0
    #pragma unroll
    for (int it = 0; it < 4; ++it)
        ar[it] = *reinterpret_cast<const float4*>(&x[(size_t)(m0 + arow[it]) * 1024 + ac4]);
    #pragma unroll
    for (int it = 0; it < 2; ++it)
        br[it] = *reinterpret_cast<const float4*>(&Wg[(size_t)(r0 + arow[it]) * 2048 + 1024 + ac4]);
    #pragma unroll
    for (int it = 0; it < 4; ++it) {
        uint32_t* w = &As[arow[it]][ac4];
        w[0]=f2tf32(ar[it].x); w[1]=f2tf32(ar[it].y); w[2]=f2tf32(ar[it].z); w[3]=f2tf32(ar[it].w);
    }
    #pragma unroll
    for (int it = 0; it < 2; ++it) {
        uint32_t* w = &Bs[arow[it]][ac4];
        w[0]=f2tf32(br[it].x); w[1]=f2tf32(br[it].y); w[2]=f2tf32(br[it].z); w[3]=f2tf32(br[it].w);
    }
    __syncthreads();

    for (int k0 = 0; k0 < 1024; k0 += 32) {
        // issue loads for next tile while doing mma on current
        if (k0 < 992) {
            #pragma unroll
            for (int it = 0; it < 4; ++it)
                ar[it] = *reinterpret_cast<const float4*>(
                    &x[(size_t)(m0 + arow[it]) * 1024 + k0 + 32 + ac4]);
            #pragma unroll
            for (int it = 0; it < 2; ++it)
                br[it] = *reinterpret_cast<const float4*>(
                    &Wg[(size_t)(r0 + arow[it]) * 2048 + 1024 + k0 + 32 + ac4]);
        }

        #pragma unroll
        for (int ks = 0; ks < 4; ++ks) {
            const int kk = ks * 8;
            uint32_t a[2][4];
            #pragma unroll
            for (int mt = 0; mt < 2; ++mt) {
                int rb = wm * 32 + mt * 16 + q;
                a[mt][0] = As[rb][kk + p];
                a[mt][1] = As[rb + 8][kk + p];
                a[mt][2] = As[rb][kk + p + 4];
                a[mt][3] = As[rb + 8][kk + p + 4];
            }
            #pragma unroll
            for (int nt = 0; nt < 4; ++nt) {
                uint32_t bb[2];
                int nr = wn * 32 + nt * 8 + q;
                bb[0] = Bs[nr][kk + p];
                bb[1] = Bs[nr][kk + p + 4];
                mma_tf32(acc[0][nt], a[0], bb);
                mma_tf32(acc[1][nt], a[1], bb);
            }
        }
        __syncthreads();
        if (k0 < 992) {
            #pragma unroll
            for (int it = 0; it < 4; ++it) {
                uint32_t* w = &As[arow[it]][ac4];
                w[0]=f2tf32(ar[it].x); w[1]=f2tf32(ar[it].y); w[2]=f2tf32(ar[it].z); w[3]=f2tf32(ar[it].w);
            }
            #pragma unroll
            for (int it = 0; it < 2; ++it) {
                uint32_t* w = &Bs[arow[it]][ac4];
                w[0]=f2tf32(br[it].x); w[1]=f2tf32(br[it].y); w[2]=f2tf32(br[it].z); w[3]=f2tf32(br[it].w);
            }
            __syncthreads();
        }
    }

    #pragma unroll
    for (int mt = 0; mt < 2; ++mt)
        #pragma unroll
        for (int nt = 0; nt < 4; ++nt)
            #pragma unroll
            for (int r = 0; r < 4; ++r) {
                int row = wm * 32 + mt * 16 + q + ((r >> 1) << 3);
                int col = wn * 32 + nt * 8 + 2 * p + (r & 1);
                int m = m0 + row;
                int b = m >> 8;
                int s = m & 255;
                g_Xp[((size_t)(s * 128 + b) * 4096) + gate * 1024 + r0 + col] =
                    acc[mt][nt][r] + bg[r0 + col];
            }
}

// ---------------------------------------------------------------------------
// Phase 2
// ---------------------------------------------------------------------------
__device__ __forceinline__ void grid_barrier() {
    __threadfence();
    if (threadIdx.x == 0) {
        unsigned old = atomicAdd(&g_arrive, 1u);
        unsigned target = (old / gridDim.x + 1u) * gridDim.x;
        while (*(volatile unsigned*)&g_arrive < target) {
            __nanosleep(64);
        }
        __threadfence();
    }
    __syncthreads();
}

__global__ void __launch_bounds__(256, 1) lstm_scan_kernel(
    const float* __restrict__ Wf, const float* __restrict__ Wi,
    const float* __restrict__ Wc, const float* __restrict__ Wo,
    float* __restrict__ out)
{
    extern __shared__ uint8_t smem[];
    uint32_t* Ws  = reinterpret_cast<uint32_t*>(smem);                       // [32][WS_STRIDE]
    uint32_t* Asb = reinterpret_cast<uint32_t*>(smem + 32 * WS_STRIDE * 4);  // [2][128][AS_STRIDE]
    float*    red = reinterpret_cast<float*>(smem + 32 * WS_STRIDE * 4);     // aliased [128][33]

    const float* Wsel[4] = {Wf, Wi, Wc, Wo};
    const int tid  = threadIdx.x;
    const int warp = tid >> 5;
    const int lane = tid & 31;
    const int q = lane >> 2, p = lane & 3;
    const int mg = warp & 3;     // m-group: batches mg*32..mg*32+31
    const int km = warp >> 2;    // k-interleave group (0/1)
    const int j0 = blockIdx.x * 8;

    const uint32_t as_base = (uint32_t)__cvta_generic_to_shared(Asb);

    // Load Wh slice (rows j0..j0+7 per gate, cols 0..1023) as tf32
    for (int idx = tid; idx < 32 * 256; idx += 256) {
        int cc = idx >> 8;
        int k4 = (idx & 255) * 4;
        int g = cc >> 3, jj = cc & 7;
        const float* Wg = Wsel[g];
        float4 v = *reinterpret_cast<const float4*>(&Wg[(size_t)(j0 + jj) * 2048 + k4]);
        uint32_t* wr = &Ws[cc * WS_STRIDE + k4];
        wr[0]=f2tf32(v.x); wr[1]=f2tf32(v.y); wr[2]=f2tf32(v.z); wr[3]=f2tf32(v.w);
    }
    // zero h buffer 0 (our columns)
    for (int idx = tid; idx < 1024; idx += 256) {
        int b = idx >> 3, jj = idx & 7;
        g_h[b * 1024 + j0 + jj] = 0u;
    }
    float cst[8];
    #pragma unroll
    for (int i = 0; i < 8; ++i) cst[i] = 0.0f;

    // staging indices (per-thread)
    int srow[8], sc4[8];
    #pragma unroll
    for (int it = 0; it < 8; ++it) {
        int idx = tid + 256 * it;
        srow[it] = idx >> 4;
        sc4[it]  = (idx & 15) * 4;
    }

    grid_barrier();

    for (int t = 0; t < 256; ++t) {
        const uint32_t* __restrict__ hin = &g_h[(t & 1) * (128 * 1024)];
        uint32_t* __restrict__ hout = &g_h[((t + 1) & 1) * (128 * 1024)];

        // prefetch Xp for this step (km==0 warps own the epilogue)
        float2 xp[4][4];
        if (km == 0) {
            #pragma unroll
            for (int rr = 0; rr < 4; ++rr) {
                int row = mg * 32 + q + rr * 8;
                size_t base = ((size_t)(t * 128 + row)) * 4096 + j0 + 2 * p;
                #pragma unroll
                for (int g = 0; g < 4; ++g)
                    xp[rr][g] = __ldg(reinterpret_cast<const float2*>(&g_Xp[base + g * 1024]));
            }
        }

        float acc[2][4][4];
        #pragma unroll
        for (int mt = 0; mt < 2; ++mt)
            #pragma unroll
            for (int nt = 0; nt < 4; ++nt)
                #pragma unroll
                for (int r = 0; r < 4; ++r) acc[mt][nt][r] = 0.0f;

        // prologue: stage chunk 0 into buf 0
        #pragma unroll
        for (int it = 0; it < 8; ++it) {
            uint32_t dsm = as_base + ((srow[it] * AS_STRIDE + sc4[it]) << 2);
            const uint32_t* src = hin + srow[it] * 1024 + sc4[it];
            asm volatile("cp.async.cg.shared.global [%0], [%1], 16;" :: "r"(dsm), "l"(src));
        }
        asm volatile("cp.async.commit_group;");

        for (int c = 0; c < 16; ++c) {
            if (c < 15) {
                uint32_t boff = (uint32_t)(((c + 1) & 1) * 128 * AS_STRIDE) << 2;
                #pragma unroll
                for (int it = 0; it < 8; ++it) {
                    uint32_t dsm = as_base + boff + ((srow[it] * AS_STRIDE + sc4[it]) << 2);
                    const uint32_t* src = hin + srow[it] * 1024 + (c + 1) * 64 + sc4[it];
                    asm volatile("cp.async.cg.shared.global [%0], [%1], 16;" :: "r"(dsm), "l"(src));
                }
                asm volatile("cp.async.commit_group;");
                asm volatile("cp.async.wait_group 1;");
            } else {
                asm volatile("cp.async.wait_group 0;");
            }
            __syncthreads();

            const uint32_t* Ab = Asb + (c & 1) * (128 * AS_STRIDE);
            #pragma unroll
            for (int s = 0; s < 4; ++s) {
                const int kk = (2 * s + km) * 8;
                const int kg = c * 64 + kk;
                uint32_t a[2][4];
                #pragma unroll
                for (int mt = 0; mt < 2; ++mt) {
                    int rb = mg * 32 + mt * 16 + q;
                    a[mt][0] = Ab[rb * AS_STRIDE + kk + p];
                    a[mt][1] = Ab[(rb + 8) * AS_STRIDE + kk + p];
                    a[mt][2] = Ab[rb * AS_STRIDE + kk + p + 4];
                    a[mt][3] = Ab[(rb + 8) * AS_STRIDE + kk + p + 4];
                }
                #pragma unroll
                for (int nt = 0; nt < 4; ++nt) {
                    uint32_t bb[2];
                    int nr = nt * 8 + q;
                    bb[0] = Ws[nr * WS_STRIDE + kg + p];
                    bb[1] = Ws[nr * WS_STRIDE + kg + p + 4];
                    mma_tf32(acc[0][nt], a[0], bb);
                    mma_tf32(acc[1][nt], a[1], bb);
                }
            }
            __syncthreads();   // protect double-buffer reuse
        }

        // cross-k reduction through smem (aliased over staging buffers)
        if (km == 1) {
            float* w = &red[(mg * 32 + lane) * 33];
            #pragma unroll
            for (int mt = 0; mt < 2; ++mt)
                #pragma unroll
                for (int nt = 0; nt < 4; ++nt)
                    #pragma unroll
                    for (int r = 0; r < 4; ++r)
                        w[mt * 16 + nt * 4 + r] = acc[mt][nt][r];
        }
        __syncthreads();
        if (km == 0) {
            const float* w = &red[(mg * 32 + lane) * 33];
            #pragma unroll
            for (int mt = 0; mt < 2; ++mt)
                #pragma unroll
                for (int nt = 0; nt < 4; ++nt)
                    #pragma unroll
                    for (int r = 0; r < 4; ++r)
                        acc[mt][nt][r] += w[mt * 16 + nt * 4 + r];

            // epilogue: 8 cells per thread
            #pragma unroll
            for (int mt = 0; mt < 2; ++mt)
                #pragma unroll
                for (int r = 0; r < 4; ++r) {
                    int rr = mt * 2 + (r >> 1);
                    int row = mg * 32 + q + rr * 8;
                    int jj = 2 * p + (r & 1);
                    float xf = (r & 1) ? xp[rr][0].y : xp[rr][0].x;
                    float xi = (r & 1) ? xp[rr][1].y : xp[rr][1].x;
                    float xg = (r & 1) ? xp[rr][2].y : xp[rr][2].x;
                    float xo = (r & 1) ? xp[rr][3].y : xp[rr][3].x;
                    float fg = sigm(acc[mt][0][r] + xf);
                    float ig = sigm(acc[mt][1][r] + xi);
                    float gg = tanhf(acc[mt][2][r] + xg);
                    float og = sigm(acc[mt][3][r] + xo);
                    float cnew = cst[mt * 4 + r] * fg + ig * gg;
                    cst[mt * 4 + r] = cnew;
                    float hnew = tanhf(cnew) * og;
                    hout[row * 1024 + j0 + jj] = f2tf32(hnew);
                    out[(size_t)row * (256 * 1024) + t * 1024 + j0 + jj] = hnew;
                }
        }
        grid_barrier();
    }
}

// ---------------------------------------------------------------------------
extern "C" void kernel_launch(void* const* d_in, const int* in_sizes, int n_in,
                              void* d_out, int out_size) {
    const float* x  = (const float*)d_in[0];
    const float* Wf = (const float*)d_in[1];
    const float* bf = (const float*)d_in[2];
    const float* Wi = (const float*)d_in[3];
    const float* bi = (const float*)d_in[4];
    const float* Wc = (const float*)d_in[5];
    const float* bc = (const float*)d_in[6];
    const float* Wo = (const float*)d_in[7];
    const float* bo = (const float*)d_in[8];
    float* out = (float*)d_out;

    cudaFuncSetAttribute(lstm_scan_kernel,
                         cudaFuncAttributeMaxDynamicSharedMemorySize, SMEM2_BYTES);

    dim3 g1(4096 / 64, 32768 / 128);
    xproj_kernel<<<g1, 256>>>(x, Wf, bf, Wi, bi, Wc, bc, Wo, bo);
    lstm_scan_kernel<<<NBLK2, 256, SMEM2_BYTES>>>(Wf, Wi, Wc, Wo, out);
}